// round 6
// baseline (speedup 1.0000x reference)
#include <cuda_runtime.h>
#include <cuda_bf16.h>
#include <math.h>
#include <stdint.h>

// Problem constants
#define BB   16
#define SS   1024
#define EE   256
#define HH   256
#define G4H  1024
#define WT   256
#define MM   (BB * SS)

// ---------------------------------------------------------------------------
// Scratch
// ---------------------------------------------------------------------------
__device__ float g_pre_f[MM * G4H];
__device__ float g_pre_b[MM * G4H];
__device__ float g_pre_d[MM * G4H];
__device__ float g_hn[MM * HH];
__device__ float g_hb[MM * HH];
__device__ float g_dh[MM * HH];
__device__ float g_q [MM * WT];
__device__ float g_p [MM * WT];

// ---------------------------------------------------------------------------
// PTX helpers
// ---------------------------------------------------------------------------
__device__ __forceinline__ uint32_t smem_u32(const void* p) {
    uint32_t a;
    asm("{ .reg .u64 t; cvta.to.shared.u64 t, %1; cvt.u32.u64 %0, t; }"
        : "=r"(a) : "l"(p));
    return a;
}
__device__ __forceinline__ void st_cluster_f32(uint32_t laddr, uint32_t rank, float v) {
    uint32_t ra;
    asm volatile("mapa.shared::cluster.u32 %0, %1, %2;" : "=r"(ra) : "r"(laddr), "r"(rank));
    asm volatile("st.shared::cluster.f32 [%0], %1;" :: "r"(ra), "f"(v) : "memory");
}
__device__ __forceinline__ void mbar_init(uint32_t a, uint32_t cnt) {
    asm volatile("mbarrier.init.shared.b64 [%0], %1;" :: "r"(a), "r"(cnt) : "memory");
}
__device__ __forceinline__ void mbar_arrive_cluster(uint32_t laddr, uint32_t rank) {
    uint32_t ra;
    asm volatile("mapa.shared::cluster.u32 %0, %1, %2;" : "=r"(ra) : "r"(laddr), "r"(rank));
    asm volatile("mbarrier.arrive.release.cluster.shared::cluster.b64 _, [%0];"
                 :: "r"(ra) : "memory");
}
__device__ __forceinline__ void mbar_wait(uint32_t a, uint32_t parity) {
    asm volatile(
        "{\n\t.reg .pred P;\n"
        "WL%=:\n\t"
        "mbarrier.try_wait.parity.acquire.cluster.shared::cta.b64 P, [%0], %1, 0x989680;\n\t"
        "@P bra WD%=;\n\t"
        "bra WL%=;\n"
        "WD%=:\n\t}"
        :: "r"(a), "r"(parity) : "memory");
}

// f32x2 packed FMA
typedef unsigned long long u64t;
__device__ __forceinline__ u64t pack2(float lo, float hi) {
    u64t r; asm("mov.b64 %0, {%1,%2};" : "=l"(r) : "f"(lo), "f"(hi)); return r;
}
__device__ __forceinline__ void unpack2(float& lo, float& hi, u64t v) {
    asm("mov.b64 {%0,%1}, %2;" : "=f"(lo), "=f"(hi) : "l"(v));
}
__device__ __forceinline__ void fma2(u64t& d, u64t a, u64t b) {
    asm("fma.rn.f32x2 %0, %1, %2, %0;" : "+l"(d) : "l"(a), "l"(b));
}

// ---------------------------------------------------------------------------
// Tiled fp32 GEMM with packed f32x2 FMA.
// C[M,N] (= or +=) A[M,K] @ Bw[K,N] (+ bias). shiftA: row m reads A[m-1],
// zeros at (m % SS)==0.
// ---------------------------------------------------------------------------
#define GBM 128
#define GBN 64
#define GBK 16

__global__ __launch_bounds__(256) void gemm_kernel(
    const float* __restrict__ A, const float* __restrict__ Bw,
    const float* __restrict__ bias, float* __restrict__ C,
    int N, int K, int shiftA, int accFlag)
{
    __shared__ __align__(16) float As[GBK][GBM + 4];
    __shared__ __align__(16) float Bs[GBK][GBN];
    const int bm  = blockIdx.y * GBM;
    const int bn  = blockIdx.x * GBN;
    const int tid = threadIdx.x;
    const int tx  = tid & 15;   // 4 cols
    const int ty  = tid >> 4;   // 8 rows (4 row-pairs)

    u64t acc2[4][4];            // [row-pair][col], lanes = 2 adjacent rows
#pragma unroll
    for (int i = 0; i < 4; i++)
#pragma unroll
        for (int j = 0; j < 4; j++) acc2[i][j] = pack2(0.f, 0.f);

    for (int k0 = 0; k0 < K; k0 += GBK) {
        {
            int kr = tid >> 4;
            int cq = tid & 15;
            float4 v = *(const float4*)(Bw + (size_t)(k0 + kr) * N + bn + cq * 4);
            *(float4*)(&Bs[kr][cq * 4]) = v;
        }
#pragma unroll
        for (int l = 0; l < 2; l++) {
            int f4 = tid + l * 256;
            int r  = f4 >> 2;
            int kq = f4 & 3;
            int gm = bm + r;
            float4 v;
            if (shiftA && ((gm & (SS - 1)) == 0)) {
                v = make_float4(0.f, 0.f, 0.f, 0.f);
            } else {
                v = *(const float4*)(A + (size_t)(gm - shiftA) * K + k0 + kq * 4);
            }
            As[kq * 4 + 0][r] = v.x;
            As[kq * 4 + 1][r] = v.y;
            As[kq * 4 + 2][r] = v.z;
            As[kq * 4 + 3][r] = v.w;
        }
        __syncthreads();
#pragma unroll
        for (int kk = 0; kk < GBK; kk++) {
            // rows: pairs packed directly from smem layout (m contiguous)
            ulonglong2 A0 = *(const ulonglong2*)(&As[kk][ty * 8]);
            ulonglong2 A1 = *(const ulonglong2*)(&As[kk][ty * 8 + 4]);
            u64t ar[4] = {A0.x, A0.y, A1.x, A1.y};
            float4 bv = *(const float4*)(&Bs[kk][tx * 4]);
            u64t bd[4] = {pack2(bv.x, bv.x), pack2(bv.y, bv.y),
                          pack2(bv.z, bv.z), pack2(bv.w, bv.w)};
#pragma unroll
            for (int i = 0; i < 4; i++)
#pragma unroll
                for (int j = 0; j < 4; j++) fma2(acc2[i][j], ar[i], bd[j]);
        }
        __syncthreads();
    }

    float4 bias4 = make_float4(0.f, 0.f, 0.f, 0.f);
    if (!accFlag && bias) bias4 = *(const float4*)(bias + bn + tx * 4);
#pragma unroll
    for (int i = 0; i < 4; i++) {
        float r0[4], r1[4];
#pragma unroll
        for (int j = 0; j < 4; j++) unpack2(r0[j], r1[j], acc2[i][j]);
#pragma unroll
        for (int h = 0; h < 2; h++) {
            float* rv = h ? r1 : r0;
            int gm = bm + ty * 8 + i * 2 + h;
            float* crow = C + (size_t)gm * N + bn + tx * 4;
            float4 v = make_float4(rv[0], rv[1], rv[2], rv[3]);
            if (accFlag) {
                float4 old = *(const float4*)crow;
                v.x += old.x; v.y += old.y; v.z += old.z; v.w += old.w;
            } else {
                v.x += bias4.x; v.y += bias4.y; v.z += bias4.z; v.w += bias4.w;
            }
            *(float4*)crow = v;
        }
    }
}

// ---------------------------------------------------------------------------
// Persistent LSTM recurrence, batch-pair interleaved.
// 64 blocks = 8 batch-pairs x 8 slices (cluster). Each block: 512 threads,
// 2 batches, 32 units/batch, 128 z-cols x 4-way k-split. Whh slice in
// registers (shared by both batches). Per-batch mbarrier sync (8 arrives);
// batch B's compute hides batch A's barrier/DSMEM latency.
// ---------------------------------------------------------------------------
__device__ __forceinline__ float sigm(float x) {
    return 1.0f / (1.0f + expf(-x));
}

__global__ __launch_bounds__(512, 1) __cluster_dims__(8, 1, 1)
void lstm_kernel(
    const float* __restrict__ pre,    // [B,S,4H]
    const float* __restrict__ Whh,    // [H,4H]
    float* __restrict__ hout,         // [B,S,H]
    const float* __restrict__ cinit,  // null, or [B,S,H]: c0 = cinit[b,S-1,:]
    int backward)
{
    const int pair = blockIdx.x >> 3;   // batch pair 0..7
    uint32_t rank;
    asm("mov.u32 %0, %%cluster_ctarank;" : "=r"(rank));
    const int slice = (int)rank;
    const int tid   = threadIdx.x;
    const int c     = tid & 127;
    const int kh    = tid >> 7;
    const int lid   = tid & 31;
    const int gcol  = ((c >> 5) << 8) + (slice << 5) + (c & 31);

    __shared__ float hs[2][2][HH];        // [batch][buf][unit]
    __shared__ float part[2][512];
    __shared__ __align__(8) unsigned long long mbar[2];

    const int bat[2] = {pair * 2, pair * 2 + 1};

    float w[64];
#pragma unroll
    for (int j = 0; j < 64; j++)
        w[j] = Whh[(size_t)(kh * 64 + j) * G4H + gcol];

    float cst[2] = {0.f, 0.f};
    float pv[2][4];
    if (tid < 32) {
#pragma unroll
        for (int bi = 0; bi < 2; bi++) {
            if (cinit)
                cst[bi] = cinit[((size_t)bat[bi] * SS + (SS - 1)) * HH + (slice << 5) + lid];
            int t0 = backward ? (SS - 1) : 0;
            const float* pr = pre + ((size_t)bat[bi] * SS + t0) * G4H + (slice << 5) + lid;
#pragma unroll
            for (int g = 0; g < 4; g++) pv[bi][g] = __ldcs(pr + g * HH);
        }
    }
    if (tid < HH) { hs[0][0][tid] = 0.f; hs[1][0][tid] = 0.f; }

    const uint32_t hs_base = smem_u32(&hs[0][0][0]);
    const uint32_t mb_base = smem_u32(&mbar[0]);
    if (tid == 0) { mbar_init(mb_base, 8); mbar_init(mb_base + 8, 8); }
    __syncthreads();
    asm volatile("barrier.cluster.arrive.aligned;" ::: "memory");
    asm volatile("barrier.cluster.wait.aligned;"   ::: "memory");

    for (int s = 0; s < SS; s++) {
        const int t  = backward ? (SS - 1 - s) : s;
        const int rb = s & 1;             // read buffer
        const int wb = rb ^ 1;            // write buffer
#pragma unroll
        for (int bi = 0; bi < 2; bi++) {
            if (s > 0) mbar_wait(mb_base + bi * 8, (s - 1) & 1);

            // matvec partial (4 accumulators)
            float a0 = 0.f, a1 = 0.f, a2 = 0.f, a3 = 0.f;
            const float* hp = &hs[bi][rb][kh * 64];
#pragma unroll
            for (int j4 = 0; j4 < 4; j4++) {
                float4 h0 = *(const float4*)(hp + j4 * 16);
                float4 h1 = *(const float4*)(hp + j4 * 16 + 4);
                float4 h2 = *(const float4*)(hp + j4 * 16 + 8);
                float4 h3 = *(const float4*)(hp + j4 * 16 + 12);
                const float* ww = w + j4 * 16;
                a0 = fmaf(h0.x, ww[0],  a0); a1 = fmaf(h0.y, ww[1],  a1);
                a2 = fmaf(h0.z, ww[2],  a2); a3 = fmaf(h0.w, ww[3],  a3);
                a0 = fmaf(h1.x, ww[4],  a0); a1 = fmaf(h1.y, ww[5],  a1);
                a2 = fmaf(h1.z, ww[6],  a2); a3 = fmaf(h1.w, ww[7],  a3);
                a0 = fmaf(h2.x, ww[8],  a0); a1 = fmaf(h2.y, ww[9],  a1);
                a2 = fmaf(h2.z, ww[10], a2); a3 = fmaf(h2.w, ww[11], a3);
                a0 = fmaf(h3.x, ww[12], a0); a1 = fmaf(h3.y, ww[13], a1);
                a2 = fmaf(h3.z, ww[14], a2); a3 = fmaf(h3.w, ww[15], a3);
            }
            part[bi][tid] = (a0 + a1) + (a2 + a3);
            __syncthreads();

            if (tid < 32) {
                float z[4];
#pragma unroll
                for (int g = 0; g < 4; g++) {
                    int pc = g * 32 + lid;
                    z[g] = (part[bi][pc] + part[bi][128 + pc])
                         + (part[bi][256 + pc] + part[bi][384 + pc]) + pv[bi][g];
                }
                if (s + 1 < SS) {
                    int tn = backward ? (SS - 2 - s) : (s + 1);
                    const float* pr = pre + ((size_t)bat[bi] * SS + tn) * G4H + (slice << 5) + lid;
#pragma unroll
                    for (int g = 0; g < 4; g++) pv[bi][g] = __ldcs(pr + g * HH);
                }
                float c2 = sigm(z[1]) * cst[bi] + sigm(z[0]) * tanhf(z[2]);
                cst[bi] = c2;
                float h2 = sigm(z[3]) * tanhf(c2);
                if (s + 1 < SS) {
                    uint32_t laddr = hs_base +
                        (uint32_t)(((bi * 2 + wb) * HH + (slice << 5) + lid) * 4);
#pragma unroll
                    for (uint32_t r = 0; r < 8; r++) st_cluster_f32(laddr, r, h2);
                }
                hout[((size_t)bat[bi] * SS + t) * HH + (slice << 5) + lid] = h2;
                __syncwarp();
                if (tid == 0 && s + 1 < SS) {
#pragma unroll
                    for (uint32_t r = 0; r < 8; r++)
                        mbar_arrive_cluster(mb_base + bi * 8, r);
                }
            }
        }
    }
    asm volatile("barrier.cluster.arrive.aligned;" ::: "memory");
    asm volatile("barrier.cluster.wait.aligned;"   ::: "memory");
}

// ---------------------------------------------------------------------------
// Pointer decisions (unchanged)
// ---------------------------------------------------------------------------
__global__ __launch_bounds__(256) void decide_kernel(
    const float* __restrict__ q, const float* __restrict__ pm,
    const float* __restrict__ vt1, float* __restrict__ out)
{
    const int b   = blockIdx.x;
    const int tid = threadIdx.x;
    __shared__ float pv[WT];
    __shared__ float v1[WT];
    __shared__ float rvals[256];
    __shared__ int   ridx[256];
    __shared__ int   r_sh;

    v1[tid] = vt1[tid];
    for (int s = tid; s < SS; s += 256) out[s * BB + b] = 0.f;
    __syncthreads();

    int t = 0;
    while (true) {
        pv[tid] = pm[((size_t)b * SS + t) * WT + tid];
        __syncthreads();

        float bv = -1e30f;
        int   bj = SS;
        for (int j = t + tid; j < SS; j += 256) {
            const float* qr = q + ((size_t)b * SS + j) * WT;
            float sacc = 0.f;
            for (int wi = 0; wi < WT; wi += 4) {
                float4 qq = *(const float4*)(qr + wi);
                sacc += tanhf(qq.x + pv[wi + 0]) * v1[wi + 0];
                sacc += tanhf(qq.y + pv[wi + 1]) * v1[wi + 1];
                sacc += tanhf(qq.z + pv[wi + 2]) * v1[wi + 2];
                sacc += tanhf(qq.w + pv[wi + 3]) * v1[wi + 3];
            }
            if (sacc > bv) { bv = sacc; bj = j; }
        }
        rvals[tid] = bv;
        ridx[tid]  = bj;
        __syncthreads();

        if (tid == 0) {
            float best = rvals[0];
            int   bi   = ridx[0];
            for (int i = 1; i < 256; i++) {
                if (rvals[i] > best || (rvals[i] == best && ridx[i] < bi)) {
                    best = rvals[i]; bi = ridx[i];
                }
            }
            out[bi * BB + b] = 1.0f;
            r_sh = bi;
        }
        __syncthreads();
        int r = r_sh;
        if (r <= t) break;
        t = r;
    }
}

// ---------------------------------------------------------------------------
// Launch — ordered so the 5th AND 6th launches are lstm_kernel (ncu -s 5 -c 1
// captures one of them, giving the recurrence profile next round).
// ---------------------------------------------------------------------------
extern "C" void kernel_launch(void* const* d_in, const int* in_sizes, int n_in,
                              void* d_out, int out_size) {
    const float* x        = (const float*)d_in[0];
    const float* eWih_f   = (const float*)d_in[1];
    const float* eWhh_f   = (const float*)d_in[2];
    const float* eb_f     = (const float*)d_in[3];
    const float* eWih_b   = (const float*)d_in[4];
    const float* eWhh_b   = (const float*)d_in[5];
    const float* eb_b     = (const float*)d_in[6];
    const float* dWih     = (const float*)d_in[7];
    const float* dWhh     = (const float*)d_in[8];
    const float* db       = (const float*)d_in[9];
    const float* W1       = (const float*)d_in[10];
    const float* W2       = (const float*)d_in[11];
    const float* W3       = (const float*)d_in[12];
    const float* W4       = (const float*)d_in[13];
    const float* vt1      = (const float*)d_in[14];
    float*       out      = (float*)d_out;

    float *pre_f, *pre_b, *pre_d, *hn, *hb, *dh, *q, *p;
    cudaGetSymbolAddress((void**)&pre_f, g_pre_f);
    cudaGetSymbolAddress((void**)&pre_b, g_pre_b);
    cudaGetSymbolAddress((void**)&pre_d, g_pre_d);
    cudaGetSymbolAddress((void**)&hn,    g_hn);
    cudaGetSymbolAddress((void**)&hb,    g_hb);
    cudaGetSymbolAddress((void**)&dh,    g_dh);
    cudaGetSymbolAddress((void**)&q,     g_q);
    cudaGetSymbolAddress((void**)&p,     g_p);

    dim3 thr(256);
    dim3 gridBig(G4H / GBN, MM / GBM);   // N=1024
    dim3 gridSml(WT / GBN, MM / GBM);    // N=256

    // 1-4: gemms that gate the encoders
    gemm_kernel<<<gridBig, thr>>>(x, eWih_f, eb_f, pre_f, G4H, EE, 0, 0);
    gemm_kernel<<<gridBig, thr>>>(x, eWih_b, eb_b, pre_b, G4H, EE, 0, 0);
    gemm_kernel<<<gridBig, thr>>>(x, dWih,   db,   pre_d, G4H, EE, 1, 0);
    gemm_kernel<<<gridSml, thr>>>(x, W3, nullptr, p, WT, EE, 0, 0);

    // 5-6: both encoder recurrences (profiled launch lands here)
    lstm_kernel<<<64, 512>>>(pre_f, eWhh_f, hn, nullptr, 0);
    lstm_kernel<<<64, 512>>>(pre_b, eWhh_b, hb, nullptr, 1);

    // 7-10: remaining gemms
    gemm_kernel<<<gridSml, thr>>>(x, W2, nullptr, q, WT, EE, 0, 0);
    gemm_kernel<<<gridBig, thr>>>(hn, dWih + (size_t)EE * G4H, nullptr, pre_d, G4H, HH, 1, 1);
    gemm_kernel<<<gridSml, thr>>>(hn, W1, nullptr, q, WT, HH, 0, 1);
    gemm_kernel<<<gridSml, thr>>>(hb, W1 + (size_t)HH * WT, nullptr, q, WT, HH, 0, 1);

    // 11-12: decoder recurrence + final projection
    lstm_kernel<<<64, 512>>>(pre_d, dWhh, dh, hn, 0);
    gemm_kernel<<<gridSml, thr>>>(dh, W4, nullptr, p, WT, HH, 0, 1);

    // 13: decisions
    decide_kernel<<<BB, 256>>>(q, p, vt1, out);
}

// round 8
// speedup vs baseline: 1.3275x; 1.3275x over previous
#include <cuda_runtime.h>
#include <cuda_bf16.h>
#include <math.h>
#include <stdint.h>

// Problem constants
#define BB   16
#define SS   1024
#define EE   256
#define HH   256
#define G4H  1024
#define WT   256
#define MM   (BB * SS)

// ---------------------------------------------------------------------------
// Scratch
// ---------------------------------------------------------------------------
__device__ float g_pre_f[MM * G4H];
__device__ float g_pre_b[MM * G4H];
__device__ float g_pre_d[MM * G4H];
__device__ float g_hn[MM * HH];
__device__ float g_hb[MM * HH];
__device__ float g_dh[MM * HH];
__device__ float g_q [MM * WT];
__device__ float g_p [MM * WT];
__device__ float g_hx[2 * BB * HH];          // double-buffered h exchange
__device__ unsigned g_bar[3 * BB * 32];      // per-(launch,batch) counters, 128B apart

// ---------------------------------------------------------------------------
// f32x2 packed FMA helpers (GEMM)
// ---------------------------------------------------------------------------
typedef unsigned long long u64t;
__device__ __forceinline__ u64t pack2(float lo, float hi) {
    u64t r; asm("mov.b64 %0, {%1,%2};" : "=l"(r) : "f"(lo), "f"(hi)); return r;
}
__device__ __forceinline__ void unpack2(float& lo, float& hi, u64t v) {
    asm("mov.b64 {%0,%1}, %2;" : "=f"(lo), "=f"(hi) : "l"(v));
}
__device__ __forceinline__ void fma2(u64t& d, u64t a, u64t b) {
    asm("fma.rn.f32x2 %0, %1, %2, %0;" : "+l"(d) : "l"(a), "l"(b));
}

// release-arrive / acquire-spin primitives (gpu scope)
__device__ __forceinline__ void red_release_add(unsigned* p, unsigned v) {
    asm volatile("red.release.gpu.global.add.u32 [%0], %1;"
                 :: "l"(p), "r"(v) : "memory");
}
__device__ __forceinline__ unsigned ld_acquire_u32(const unsigned* p) {
    unsigned v;
    asm volatile("ld.acquire.gpu.global.u32 %0, [%1];" : "=r"(v) : "l"(p) : "memory");
    return v;
}

// ---------------------------------------------------------------------------
// Barrier-counter init (first node of the graph; re-zeroes each replay)
// ---------------------------------------------------------------------------
__global__ void init_bar_kernel() {
    int i = blockIdx.x * blockDim.x + threadIdx.x;
    if (i < 3 * BB * 32) g_bar[i] = 0u;
}

// ---------------------------------------------------------------------------
// Tiled fp32 GEMM with packed f32x2 FMA.
// C[M,N] (= or +=) A[M,K] @ Bw[K,N] (+ bias). shiftA: row m reads A[m-1],
// zeros at (m % SS)==0.
// ---------------------------------------------------------------------------
#define GBM 128
#define GBN 64
#define GBK 16

__global__ __launch_bounds__(256) void gemm_kernel(
    const float* __restrict__ A, const float* __restrict__ Bw,
    const float* __restrict__ bias, float* __restrict__ C,
    int N, int K, int shiftA, int accFlag)
{
    __shared__ __align__(16) float As[GBK][GBM + 4];
    __shared__ __align__(16) float Bs[GBK][GBN];
    const int bm  = blockIdx.y * GBM;
    const int bn  = blockIdx.x * GBN;
    const int tid = threadIdx.x;
    const int tx  = tid & 15;
    const int ty  = tid >> 4;

    u64t acc2[4][4];
#pragma unroll
    for (int i = 0; i < 4; i++)
#pragma unroll
        for (int j = 0; j < 4; j++) acc2[i][j] = pack2(0.f, 0.f);

    for (int k0 = 0; k0 < K; k0 += GBK) {
        {
            int kr = tid >> 4;
            int cq = tid & 15;
            float4 v = *(const float4*)(Bw + (size_t)(k0 + kr) * N + bn + cq * 4);
            *(float4*)(&Bs[kr][cq * 4]) = v;
        }
#pragma unroll
        for (int l = 0; l < 2; l++) {
            int f4 = tid + l * 256;
            int r  = f4 >> 2;
            int kq = f4 & 3;
            int gm = bm + r;
            float4 v;
            if (shiftA && ((gm & (SS - 1)) == 0)) {
                v = make_float4(0.f, 0.f, 0.f, 0.f);
            } else {
                v = *(const float4*)(A + (size_t)(gm - shiftA) * K + k0 + kq * 4);
            }
            As[kq * 4 + 0][r] = v.x;
            As[kq * 4 + 1][r] = v.y;
            As[kq * 4 + 2][r] = v.z;
            As[kq * 4 + 3][r] = v.w;
        }
        __syncthreads();
#pragma unroll
        for (int kk = 0; kk < GBK; kk++) {
            ulonglong2 A0 = *(const ulonglong2*)(&As[kk][ty * 8]);
            ulonglong2 A1 = *(const ulonglong2*)(&As[kk][ty * 8 + 4]);
            u64t ar[4] = {A0.x, A0.y, A1.x, A1.y};
            float4 bv = *(const float4*)(&Bs[kk][tx * 4]);
            u64t bd[4] = {pack2(bv.x, bv.x), pack2(bv.y, bv.y),
                          pack2(bv.z, bv.z), pack2(bv.w, bv.w)};
#pragma unroll
            for (int i = 0; i < 4; i++)
#pragma unroll
                for (int j = 0; j < 4; j++) fma2(acc2[i][j], ar[i], bd[j]);
        }
        __syncthreads();
    }

    float4 bias4 = make_float4(0.f, 0.f, 0.f, 0.f);
    if (!accFlag && bias) bias4 = *(const float4*)(bias + bn + tx * 4);
#pragma unroll
    for (int i = 0; i < 4; i++) {
        float r0[4], r1[4];
#pragma unroll
        for (int j = 0; j < 4; j++) unpack2(r0[j], r1[j], acc2[i][j]);
#pragma unroll
        for (int h = 0; h < 2; h++) {
            float* rv = h ? r1 : r0;
            int gm = bm + ty * 8 + i * 2 + h;
            float* crow = C + (size_t)gm * N + bn + tx * 4;
            float4 v = make_float4(rv[0], rv[1], rv[2], rv[3]);
            if (accFlag) {
                float4 old = *(const float4*)crow;
                v.x += old.x; v.y += old.y; v.z += old.z; v.w += old.w;
            } else {
                v.x += bias4.x; v.y += bias4.y; v.z += bias4.z; v.w += bias4.w;
            }
            *(float4*)crow = v;
        }
    }
}

// ---------------------------------------------------------------------------
// Persistent LSTM recurrence. 128 blocks = 16 batches x 8 slices, 512 thr.
// Whh slice register-resident. h exchanged via L2 (__stcg/__ldcg) with a
// per-batch 8-block barrier on a private 128B line.
// SOUND PROTOCOL: every producing lane arrives with red.release.gpu (its own
// release covers its own store); reader spins with ld.acquire.gpu; the
// acquire edge is propagated block-wide by bar.sync before hs is loaded.
// ---------------------------------------------------------------------------
__device__ __forceinline__ float sigm(float x) {
    return 1.0f / (1.0f + expf(-x));
}

__global__ __launch_bounds__(512, 1) void lstm_kernel(
    const float* __restrict__ pre,    // [B,S,4H]
    const float* __restrict__ Whh,    // [H,4H]
    float* __restrict__ hout,         // [B,S,H]
    const float* __restrict__ cinit,  // null, or [B,S,H]: c0 = cinit[b,S-1,:]
    int backward, int slot)
{
    const int blk   = blockIdx.x;
    const int batch = blk >> 3;
    const int slice = blk & 7;
    const int tid   = threadIdx.x;
    const int c     = tid & 127;
    const int kh    = tid >> 7;
    const int lid   = tid & 31;
    const int gcol  = ((c >> 5) << 8) + (slice << 5) + (c & 31); // gate*256+unit

    __shared__ float hs[HH];
    __shared__ float part[512];

    unsigned* barp = &g_bar[(slot * BB + batch) * 32];

    float w[64];
#pragma unroll
    for (int j = 0; j < 64; j++)
        w[j] = Whh[(size_t)(kh * 64 + j) * G4H + gcol];

    float cst = 0.f;
    float pv[4];
    if (tid < 32) {
        if (cinit)
            cst = cinit[((size_t)batch * SS + (SS - 1)) * HH + (slice << 5) + lid];
        int t0 = backward ? (SS - 1) : 0;
        const float* pr = pre + ((size_t)batch * SS + t0) * G4H + (slice << 5) + lid;
#pragma unroll
        for (int g = 0; g < 4; g++) pv[g] = __ldcs(pr + g * HH);
    }
    if (tid < HH) hs[tid] = 0.f;   // h0 = 0
    __syncthreads();

    for (int s = 0; s < SS; s++) {
        const int t = backward ? (SS - 1 - s) : s;

        // load current h into smem (s=0: zeros already there)
        if (s > 0 && tid < HH / 4) {
            const float4* hrd =
                (const float4*)(g_hx + (s & 1) * (BB * HH) + batch * HH);
            *(float4*)(&hs[tid * 4]) = __ldcg(hrd + tid);
        }
        __syncthreads();

        // matvec partial: 64 k per thread (warp-uniform smem broadcast reads)
        float a0 = 0.f, a1 = 0.f, a2 = 0.f, a3 = 0.f;
        const float* hp = &hs[kh * 64];
#pragma unroll
        for (int j4 = 0; j4 < 4; j4++) {
            float4 h0 = *(const float4*)(hp + j4 * 16);
            float4 h1 = *(const float4*)(hp + j4 * 16 + 4);
            float4 h2v = *(const float4*)(hp + j4 * 16 + 8);
            float4 h3 = *(const float4*)(hp + j4 * 16 + 12);
            const float* ww = w + j4 * 16;
            a0 = fmaf(h0.x, ww[0],  a0); a1 = fmaf(h0.y, ww[1],  a1);
            a2 = fmaf(h0.z, ww[2],  a2); a3 = fmaf(h0.w, ww[3],  a3);
            a0 = fmaf(h1.x, ww[4],  a0); a1 = fmaf(h1.y, ww[5],  a1);
            a2 = fmaf(h1.z, ww[6],  a2); a3 = fmaf(h1.w, ww[7],  a3);
            a0 = fmaf(h2v.x, ww[8],  a0); a1 = fmaf(h2v.y, ww[9],  a1);
            a2 = fmaf(h2v.z, ww[10], a2); a3 = fmaf(h2v.w, ww[11], a3);
            a0 = fmaf(h3.x, ww[12], a0); a1 = fmaf(h3.y, ww[13], a1);
            a2 = fmaf(h3.z, ww[14], a2); a3 = fmaf(h3.w, ww[15], a3);
        }
        part[tid] = (a0 + a1) + (a2 + a3);
        __syncthreads();

        if (tid < 32) {
            float z[4];
#pragma unroll
            for (int g = 0; g < 4; g++) {
                int pc = g * 32 + lid;
                z[g] = (part[pc] + part[128 + pc])
                     + (part[256 + pc] + part[384 + pc]) + pv[g];
            }
            // prefetch NEXT step's pre (consumed a full step later)
            if (s + 1 < SS) {
                int tn = backward ? (SS - 2 - s) : (s + 1);
                const float* pr =
                    pre + ((size_t)batch * SS + tn) * G4H + (slice << 5) + lid;
#pragma unroll
                for (int g = 0; g < 4; g++) pv[g] = __ldcs(pr + g * HH);
            }
            float c2 = sigm(z[1]) * cst + sigm(z[0]) * tanhf(z[2]);
            cst = c2;
            float h2 = sigm(z[3]) * tanhf(c2);
            hout[((size_t)batch * SS + t) * HH + (slice << 5) + lid] = h2;
            if (s + 1 < SS) {
                // publish h for step s+1: L2 store + per-lane release-arrive
                __stcg(&g_hx[((s + 1) & 1) * (BB * HH) + batch * HH
                             + (slice << 5) + lid], h2);
                red_release_add(barp, 1u);   // ALL 32 lanes arrive
                // wait until all 8 blocks' 32 lanes arrived for this step
                if (lid == 0) {
                    unsigned tgt = 256u * (unsigned)(s + 1);
                    while (ld_acquire_u32(barp) < tgt) { }
                }
                __syncwarp();
            }
        }
        // propagate warp0's acquire to the whole block; also protects
        // part[]/hs[] reuse next iteration.
        __syncthreads();
    }
}

// ---------------------------------------------------------------------------
// Pointer decisions (unchanged; rel_err 0.0 across rounds)
// ---------------------------------------------------------------------------
__global__ __launch_bounds__(256) void decide_kernel(
    const float* __restrict__ q, const float* __restrict__ pm,
    const float* __restrict__ vt1, float* __restrict__ out)
{
    const int b   = blockIdx.x;
    const int tid = threadIdx.x;
    __shared__ float pv[WT];
    __shared__ float v1[WT];
    __shared__ float rvals[256];
    __shared__ int   ridx[256];
    __shared__ int   r_sh;

    v1[tid] = vt1[tid];
    for (int s = tid; s < SS; s += 256) out[s * BB + b] = 0.f;
    __syncthreads();

    int t = 0;
    while (true) {
        pv[tid] = pm[((size_t)b * SS + t) * WT + tid];
        __syncthreads();

        float bv = -1e30f;
        int   bj = SS;
        for (int j = t + tid; j < SS; j += 256) {
            const float* qr = q + ((size_t)b * SS + j) * WT;
            float sacc = 0.f;
            for (int wi = 0; wi < WT; wi += 4) {
                float4 qq = *(const float4*)(qr + wi);
                sacc += tanhf(qq.x + pv[wi + 0]) * v1[wi + 0];
                sacc += tanhf(qq.y + pv[wi + 1]) * v1[wi + 1];
                sacc += tanhf(qq.z + pv[wi + 2]) * v1[wi + 2];
                sacc += tanhf(qq.w + pv[wi + 3]) * v1[wi + 3];
            }
            if (sacc > bv) { bv = sacc; bj = j; }
        }
        rvals[tid] = bv;
        ridx[tid]  = bj;
        __syncthreads();

        if (tid == 0) {
            float best = rvals[0];
            int   bi   = ridx[0];
            for (int i = 1; i < 256; i++) {
                if (rvals[i] > best || (rvals[i] == best && ridx[i] < bi)) {
                    best = rvals[i]; bi = ridx[i];
                }
            }
            out[bi * BB + b] = 1.0f;
            r_sh = bi;
        }
        __syncthreads();
        int r = r_sh;
        if (r <= t) break;
        t = r;
    }
}

// ---------------------------------------------------------------------------
// Launch. Harness prepends 2 launches; ncu -s 5 captures MY 4th launch,
// which is lstm_kernel (fwd).
// ---------------------------------------------------------------------------
extern "C" void kernel_launch(void* const* d_in, const int* in_sizes, int n_in,
                              void* d_out, int out_size) {
    const float* x        = (const float*)d_in[0];
    const float* eWih_f   = (const float*)d_in[1];
    const float* eWhh_f   = (const float*)d_in[2];
    const float* eb_f     = (const float*)d_in[3];
    const float* eWih_b   = (const float*)d_in[4];
    const float* eWhh_b   = (const float*)d_in[5];
    const float* eb_b     = (const float*)d_in[6];
    const float* dWih     = (const float*)d_in[7];
    const float* dWhh     = (const float*)d_in[8];
    const float* db       = (const float*)d_in[9];
    const float* W1       = (const float*)d_in[10];
    const float* W2       = (const float*)d_in[11];
    const float* W3       = (const float*)d_in[12];
    const float* W4       = (const float*)d_in[13];
    const float* vt1      = (const float*)d_in[14];
    float*       out      = (float*)d_out;

    float *pre_f, *pre_b, *pre_d, *hn, *hb, *dh, *q, *p;
    cudaGetSymbolAddress((void**)&pre_f, g_pre_f);
    cudaGetSymbolAddress((void**)&pre_b, g_pre_b);
    cudaGetSymbolAddress((void**)&pre_d, g_pre_d);
    cudaGetSymbolAddress((void**)&hn,    g_hn);
    cudaGetSymbolAddress((void**)&hb,    g_hb);
    cudaGetSymbolAddress((void**)&dh,    g_dh);
    cudaGetSymbolAddress((void**)&q,     g_q);
    cudaGetSymbolAddress((void**)&p,     g_p);

    dim3 thr(256);
    dim3 gridBig(G4H / GBN, MM / GBM);   // N=1024
    dim3 gridSml(WT / GBN, MM / GBM);    // N=256

    // 1: reset per-batch barrier counters (runs on every graph replay)
    init_bar_kernel<<<6, 256>>>();

    // 2-3: encoder pre-activation gemms
    gemm_kernel<<<gridBig, thr>>>(x, eWih_f, eb_f, pre_f, G4H, EE, 0, 0);
    gemm_kernel<<<gridBig, thr>>>(x, eWih_b, eb_b, pre_b, G4H, EE, 0, 0);

    // 4: forward encoder recurrence  <-- ncu capture slot (-s 5, 2 prepended)
    lstm_kernel<<<128, 512>>>(pre_f, eWhh_f, hn, nullptr, 0, 0);

    // 5-7: gemms independent of hb/dh + backward encoder
    gemm_kernel<<<gridBig, thr>>>(x, dWih,   db,   pre_d, G4H, EE, 1, 0);
    gemm_kernel<<<gridSml, thr>>>(x, W3, nullptr, p, WT, EE, 0, 0);
    lstm_kernel<<<128, 512>>>(pre_b, eWhh_b, hb, nullptr, 1, 1);

    // 8-11: remaining projections
    gemm_kernel<<<gridSml, thr>>>(x, W2, nullptr, q, WT, EE, 0, 0);
    gemm_kernel<<<gridBig, thr>>>(hn, dWih + (size_t)EE * G4H, nullptr, pre_d, G4H, HH, 1, 1);
    gemm_kernel<<<gridSml, thr>>>(hn, W1, nullptr, q, WT, HH, 0, 1);
    gemm_kernel<<<gridSml, thr>>>(hb, W1 + (size_t)HH * WT, nullptr, q, WT, HH, 0, 1);

    // 12-13: decoder recurrence + final projection
    lstm_kernel<<<128, 512>>>(pre_d, dWhh, dh, hn, 0, 2);
    gemm_kernel<<<gridSml, thr>>>(dh, W4, nullptr, p, WT, HH, 0, 1);

    // 14: decisions
    decide_kernel<<<BB, 256>>>(q, p, vt1, out);
}

// round 11
// speedup vs baseline: 1.5109x; 1.1381x over previous
#include <cuda_runtime.h>
#include <cuda_bf16.h>
#include <math.h>
#include <stdint.h>

// Problem constants
#define BB   16
#define SS   1024
#define EE   256
#define HH   256
#define G4H  1024
#define WT   256
#define MM   (BB * SS)

// ---------------------------------------------------------------------------
// Scratch
// ---------------------------------------------------------------------------
__device__ float g_pre_f[MM * G4H];
__device__ float g_pre_b[MM * G4H];
__device__ float g_pre_d[MM * G4H];
__device__ float g_hn[MM * HH];
__device__ float g_hb[MM * HH];
__device__ float g_dh[MM * HH];
__device__ float g_q [MM * WT];
__device__ float g_p [MM * WT];

// ---------------------------------------------------------------------------
// PTX helpers
// ---------------------------------------------------------------------------
typedef unsigned long long u64t;
__device__ __forceinline__ u64t pack2(float lo, float hi) {
    u64t r; asm("mov.b64 %0, {%1,%2};" : "=l"(r) : "f"(lo), "f"(hi)); return r;
}
__device__ __forceinline__ void unpack2(float& lo, float& hi, u64t v) {
    asm("mov.b64 {%0,%1}, %2;" : "=f"(lo), "=f"(hi) : "l"(v));
}
__device__ __forceinline__ void fma2(u64t& d, u64t a, u64t b) {
    asm("fma.rn.f32x2 %0, %1, %2, %0;" : "+l"(d) : "l"(a), "l"(b));
}
__device__ __forceinline__ uint32_t smem_u32(const void* p) {
    uint32_t a;
    asm("{ .reg .u64 t; cvta.to.shared.u64 t, %1; cvt.u32.u64 %0, t; }"
        : "=r"(a) : "l"(p));
    return a;
}
__device__ __forceinline__ void st_cluster_f32(uint32_t laddr, uint32_t rank, float v) {
    uint32_t ra;
    asm volatile("mapa.shared::cluster.u32 %0, %1, %2;" : "=r"(ra) : "r"(laddr), "r"(rank));
    asm volatile("st.shared::cluster.f32 [%0], %1;" :: "r"(ra), "f"(v) : "memory");
}
__device__ __forceinline__ void mbar_init(uint32_t a, uint32_t cnt) {
    asm volatile("mbarrier.init.shared.b64 [%0], %1;" :: "r"(a), "r"(cnt) : "memory");
}
__device__ __forceinline__ void mbar_arrive_cluster(uint32_t laddr, uint32_t rank) {
    uint32_t ra;
    asm volatile("mapa.shared::cluster.u32 %0, %1, %2;" : "=r"(ra) : "r"(laddr), "r"(rank));
    asm volatile("mbarrier.arrive.release.cluster.shared::cluster.b64 _, [%0];"
                 :: "r"(ra) : "memory");
}
__device__ __forceinline__ void mbar_wait(uint32_t a, uint32_t parity) {
    asm volatile(
        "{\n\t.reg .pred P;\n"
        "WL%=:\n\t"
        "mbarrier.try_wait.parity.acquire.cluster.shared::cta.b64 P, [%0], %1, 0x989680;\n\t"
        "@P bra WD%=;\n\t"
        "bra WL%=;\n"
        "WD%=:\n\t}"
        :: "r"(a), "r"(parity) : "memory");
}

// fast activations (err ~1e-6; safe for downstream argmax, unlike tanh.approx)
__device__ __forceinline__ float sigm_fast(float x) {
    return __fdividef(1.0f, 1.0f + __expf(-x));
}
__device__ __forceinline__ float tanh_fast(float x) {
    return 1.0f - __fdividef(2.0f, __expf(2.0f * x) + 1.0f);
}

// ---------------------------------------------------------------------------
// Tiled fp32 GEMM with packed f32x2 FMA (unchanged; measured ~60us @ N=256).
// ---------------------------------------------------------------------------
#define GBM 128
#define GBN 64
#define GBK 16

__global__ __launch_bounds__(256) void gemm_kernel(
    const float* __restrict__ A, const float* __restrict__ Bw,
    const float* __restrict__ bias, float* __restrict__ C,
    int N, int K, int shiftA, int accFlag)
{
    __shared__ __align__(16) float As[GBK][GBM + 4];
    __shared__ __align__(16) float Bs[GBK][GBN];
    const int bm  = blockIdx.y * GBM;
    const int bn  = blockIdx.x * GBN;
    const int tid = threadIdx.x;
    const int tx  = tid & 15;
    const int ty  = tid >> 4;

    u64t acc2[4][4];
#pragma unroll
    for (int i = 0; i < 4; i++)
#pragma unroll
        for (int j = 0; j < 4; j++) acc2[i][j] = pack2(0.f, 0.f);

    for (int k0 = 0; k0 < K; k0 += GBK) {
        {
            int kr = tid >> 4;
            int cq = tid & 15;
            float4 v = *(const float4*)(Bw + (size_t)(k0 + kr) * N + bn + cq * 4);
            *(float4*)(&Bs[kr][cq * 4]) = v;
        }
#pragma unroll
        for (int l = 0; l < 2; l++) {
            int f4 = tid + l * 256;
            int r  = f4 >> 2;
            int kq = f4 & 3;
            int gm = bm + r;
            float4 v;
            if (shiftA && ((gm & (SS - 1)) == 0)) {
                v = make_float4(0.f, 0.f, 0.f, 0.f);
            } else {
                v = *(const float4*)(A + (size_t)(gm - shiftA) * K + k0 + kq * 4);
            }
            As[kq * 4 + 0][r] = v.x;
            As[kq * 4 + 1][r] = v.y;
            As[kq * 4 + 2][r] = v.z;
            As[kq * 4 + 3][r] = v.w;
        }
        __syncthreads();
#pragma unroll
        for (int kk = 0; kk < GBK; kk++) {
            ulonglong2 A0 = *(const ulonglong2*)(&As[kk][ty * 8]);
            ulonglong2 A1 = *(const ulonglong2*)(&As[kk][ty * 8 + 4]);
            u64t ar[4] = {A0.x, A0.y, A1.x, A1.y};
            float4 bv = *(const float4*)(&Bs[kk][tx * 4]);
            u64t bd[4] = {pack2(bv.x, bv.x), pack2(bv.y, bv.y),
                          pack2(bv.z, bv.z), pack2(bv.w, bv.w)};
#pragma unroll
            for (int i = 0; i < 4; i++)
#pragma unroll
                for (int j = 0; j < 4; j++) fma2(acc2[i][j], ar[i], bd[j]);
        }
        __syncthreads();
    }

    float4 bias4 = make_float4(0.f, 0.f, 0.f, 0.f);
    if (!accFlag && bias) bias4 = *(const float4*)(bias + bn + tx * 4);
#pragma unroll
    for (int i = 0; i < 4; i++) {
        float r0[4], r1[4];
#pragma unroll
        for (int j = 0; j < 4; j++) unpack2(r0[j], r1[j], acc2[i][j]);
#pragma unroll
        for (int h = 0; h < 2; h++) {
            float* rv = h ? r1 : r0;
            int gm = bm + ty * 8 + i * 2 + h;
            float* crow = C + (size_t)gm * N + bn + tx * 4;
            float4 v = make_float4(rv[0], rv[1], rv[2], rv[3]);
            if (accFlag) {
                float4 old = *(const float4*)crow;
                v.x += old.x; v.y += old.y; v.z += old.z; v.w += old.w;
            } else {
                v.x += bias4.x; v.y += bias4.y; v.z += bias4.z; v.w += bias4.w;
            }
            *(float4*)crow = v;
        }
    }
}

// ---------------------------------------------------------------------------
// Persistent LSTM recurrence, CGA-cluster version with DSMEM h push +
// parallel mbarrier sync.
// 128 blocks = 16 batches x 8 slices (cluster of 8). 512 threads.
// Whh slice register-resident as f32x2 pairs (32 FFMA2 per thread per step).
// Per step: 1 mbar wait + 1 __syncthreads. Producers (warp 0) push h2
// directly into all 8 peers' smem (double-buffered) and arrive on all 8
// peers' mbarriers via lanes 0-7 (parallel, release-ordered after stores
// by __syncwarp). Dependency analysis: part[]/hs[] reuse is ordered by the
// mbar chain, so no extra barriers are needed.
// ---------------------------------------------------------------------------
__global__ __launch_bounds__(512, 1) __cluster_dims__(8, 1, 1)
void lstm_kernel(
    const float* __restrict__ pre,    // [B,S,4H]
    const float* __restrict__ Whh,    // [H,4H]
    float* __restrict__ hout,         // [B,S,H]
    const float* __restrict__ cinit,  // null, or [B,S,H]: c0 = cinit[b,S-1,:]
    int backward)
{
    const int batch = blockIdx.x >> 3;
    uint32_t rank;
    asm("mov.u32 %0, %%cluster_ctarank;" : "=r"(rank));
    const int slice = (int)rank;
    const int tid   = threadIdx.x;
    const int c     = tid & 127;
    const int kh    = tid >> 7;
    const int lid   = tid & 31;
    const int gcol  = ((c >> 5) << 8) + (slice << 5) + (c & 31); // gate*256+unit

    __shared__ __align__(16) float hs[2][HH];
    __shared__ float part[512];
    __shared__ __align__(8) unsigned long long mbar;

    // register-resident Whh slice, packed as f32x2 (k, k+1)
    u64t w2[32];
#pragma unroll
    for (int j = 0; j < 32; j++) {
        float wl = Whh[(size_t)(kh * 64 + 2 * j)     * G4H + gcol];
        float wh = Whh[(size_t)(kh * 64 + 2 * j + 1) * G4H + gcol];
        w2[j] = pack2(wl, wh);
    }

    float cst = 0.f;
    float pv[4];
    if (tid < 32) {
        if (cinit)
            cst = cinit[((size_t)batch * SS + (SS - 1)) * HH + (slice << 5) + lid];
        int t0 = backward ? (SS - 1) : 0;
        const float* pr = pre + ((size_t)batch * SS + t0) * G4H + (slice << 5) + lid;
#pragma unroll
        for (int g = 0; g < 4; g++) pv[g] = __ldcs(pr + g * HH);
    }
    if (tid < HH) hs[0][tid] = 0.f;   // h0 = 0

    const uint32_t hs_base = smem_u32(&hs[0][0]);
    const uint32_t mb_base = smem_u32(&mbar);
    if (tid == 0) mbar_init(mb_base, 8);
    __syncthreads();
    // peers' mbarriers + hs[0] must be initialized before any remote traffic
    asm volatile("barrier.cluster.arrive.aligned;" ::: "memory");
    asm volatile("barrier.cluster.wait.aligned;"   ::: "memory");

    for (int s = 0; s < SS; s++) {
        const int t = backward ? (SS - 1 - s) : s;

        // wait for this step's h (delivered into hs[s&1] by all 8 CTAs)
        if (s > 0) mbar_wait(mb_base, (s - 1) & 1);

        // matvec partial: 64 k per thread as 32 packed FFMA2
        const float2* hp = (const float2*)&hs[s & 1][kh * 64];
        u64t acc0 = pack2(0.f, 0.f), acc1 = acc0, acc2v = acc0, acc3 = acc0;
#pragma unroll
        for (int j = 0; j < 8; j++) {
            ulonglong2 hq0 = *(const ulonglong2*)(hp + j * 4);
            ulonglong2 hq1 = *(const ulonglong2*)(hp + j * 4 + 2);
            fma2(acc0, hq0.x, w2[j * 4 + 0]);
            fma2(acc1, hq0.y, w2[j * 4 + 1]);
            fma2(acc2v, hq1.x, w2[j * 4 + 2]);
            fma2(acc3, hq1.y, w2[j * 4 + 3]);
        }
        float l0, h0, l1, h1, l2, h2v, l3, h3;
        unpack2(l0, h0, acc0); unpack2(l1, h1, acc1);
        unpack2(l2, h2v, acc2v); unpack2(l3, h3, acc3);
        part[tid] = ((l0 + h0) + (l1 + h1)) + ((l2 + h2v) + (l3 + h3));
        __syncthreads();

        if (tid < 32) {
            float z[4];
#pragma unroll
            for (int g = 0; g < 4; g++) {
                int pc = g * 32 + lid;
                z[g] = (part[pc] + part[128 + pc])
                     + (part[256 + pc] + part[384 + pc]) + pv[g];
            }
            // prefetch NEXT step's pre (consumed a full step later)
            if (s + 1 < SS) {
                int tn = backward ? (SS - 2 - s) : (s + 1);
                const float* pr =
                    pre + ((size_t)batch * SS + tn) * G4H + (slice << 5) + lid;
#pragma unroll
                for (int g = 0; g < 4; g++) pv[g] = __ldcs(pr + g * HH);
            }
            float c2 = sigm_fast(z[1]) * cst + sigm_fast(z[0]) * tanh_fast(z[2]);
            cst = c2;
            float h2 = sigm_fast(z[3]) * tanh_fast(c2);
            hout[((size_t)batch * SS + t) * HH + (slice << 5) + lid] = h2;
            if (s + 1 < SS) {
                // push h2 into every cluster CTA's next buffer
                uint32_t laddr = hs_base +
                    (uint32_t)((((s + 1) & 1) * HH + (slice << 5) + lid) * 4);
#pragma unroll
                for (uint32_t r = 0; r < 8; r++) st_cluster_f32(laddr, r, h2);
                __syncwarp();                 // order all lanes' stores...
                if (lid < 8)                  // ...before the release-arrives
                    mbar_arrive_cluster(mb_base, (uint32_t)lid);
            }
        }
        // NOTE: no trailing __syncthreads needed — next-step part[] writes are
        // ordered after warp0's part[] reads via this CTA's own mbar arrive.
    }
}

// ---------------------------------------------------------------------------
// Pointer decisions (unchanged; rel_err 0.0 across rounds)
// ---------------------------------------------------------------------------
__global__ __launch_bounds__(256) void decide_kernel(
    const float* __restrict__ q, const float* __restrict__ pm,
    const float* __restrict__ vt1, float* __restrict__ out)
{
    const int b   = blockIdx.x;
    const int tid = threadIdx.x;
    __shared__ float pv[WT];
    __shared__ float v1[WT];
    __shared__ float rvals[256];
    __shared__ int   ridx[256];
    __shared__ int   r_sh;

    v1[tid] = vt1[tid];
    for (int s = tid; s < SS; s += 256) out[s * BB + b] = 0.f;
    __syncthreads();

    int t = 0;
    while (true) {
        pv[tid] = pm[((size_t)b * SS + t) * WT + tid];
        __syncthreads();

        float bv = -1e30f;
        int   bj = SS;
        for (int j = t + tid; j < SS; j += 256) {
            const float* qr = q + ((size_t)b * SS + j) * WT;
            float sacc = 0.f;
            for (int wi = 0; wi < WT; wi += 4) {
                float4 qq = *(const float4*)(qr + wi);
                sacc += tanhf(qq.x + pv[wi + 0]) * v1[wi + 0];
                sacc += tanhf(qq.y + pv[wi + 1]) * v1[wi + 1];
                sacc += tanhf(qq.z + pv[wi + 2]) * v1[wi + 2];
                sacc += tanhf(qq.w + pv[wi + 3]) * v1[wi + 3];
            }
            if (sacc > bv) { bv = sacc; bj = j; }
        }
        rvals[tid] = bv;
        ridx[tid]  = bj;
        __syncthreads();

        if (tid == 0) {
            float best = rvals[0];
            int   bi   = ridx[0];
            for (int i = 1; i < 256; i++) {
                if (rvals[i] > best || (rvals[i] == best && ridx[i] < bi)) {
                    best = rvals[i]; bi = ridx[i];
                }
            }
            out[bi * BB + b] = 1.0f;
            r_sh = bi;
        }
        __syncthreads();
        int r = r_sh;
        if (r <= t) break;
        t = r;
    }
}

// ---------------------------------------------------------------------------
// Launch (lstm fwd kept as my 4th launch for the ncu capture slot)
// ---------------------------------------------------------------------------
extern "C" void kernel_launch(void* const* d_in, const int* in_sizes, int n_in,
                              void* d_out, int out_size) {
    const float* x        = (const float*)d_in[0];
    const float* eWih_f   = (const float*)d_in[1];
    const float* eWhh_f   = (const float*)d_in[2];
    const float* eb_f     = (const float*)d_in[3];
    const float* eWih_b   = (const float*)d_in[4];
    const float* eWhh_b   = (const float*)d_in[5];
    const float* eb_b     = (const float*)d_in[6];
    const float* dWih     = (const float*)d_in[7];
    const float* dWhh     = (const float*)d_in[8];
    const float* db       = (const float*)d_in[9];
    const float* W1       = (const float*)d_in[10];
    const float* W2       = (const float*)d_in[11];
    const float* W3       = (const float*)d_in[12];
    const float* W4       = (const float*)d_in[13];
    const float* vt1      = (const float*)d_in[14];
    float*       out      = (float*)d_out;

    float *pre_f, *pre_b, *pre_d, *hn, *hb, *dh, *q, *p;
    cudaGetSymbolAddress((void**)&pre_f, g_pre_f);
    cudaGetSymbolAddress((void**)&pre_b, g_pre_b);
    cudaGetSymbolAddress((void**)&pre_d, g_pre_d);
    cudaGetSymbolAddress((void**)&hn,    g_hn);
    cudaGetSymbolAddress((void**)&hb,    g_hb);
    cudaGetSymbolAddress((void**)&dh,    g_dh);
    cudaGetSymbolAddress((void**)&q,     g_q);
    cudaGetSymbolAddress((void**)&p,     g_p);

    dim3 thr(256);
    dim3 gridBig(G4H / GBN, MM / GBM);   // N=1024
    dim3 gridSml(WT / GBN, MM / GBM);    // N=256

    // 1-3: encoder pre-activation gemms + one attention gemm
    gemm_kernel<<<gridBig, thr>>>(x, eWih_f, eb_f, pre_f, G4H, EE, 0, 0);
    gemm_kernel<<<gridBig, thr>>>(x, eWih_b, eb_b, pre_b, G4H, EE, 0, 0);
    gemm_kernel<<<gridSml, thr>>>(x, W3, nullptr, p, WT, EE, 0, 0);

    // 4: forward encoder recurrence  <-- ncu capture slot
    lstm_kernel<<<128, 512>>>(pre_f, eWhh_f, hn, nullptr, 0);

    // 5-6: backward encoder + shifted-x part of decoder pre
    lstm_kernel<<<128, 512>>>(pre_b, eWhh_b, hb, nullptr, 1);
    gemm_kernel<<<gridBig, thr>>>(x, dWih,   db,   pre_d, G4H, EE, 1, 0);

    // 7-10: remaining projections
    gemm_kernel<<<gridSml, thr>>>(x, W2, nullptr, q, WT, EE, 0, 0);
    gemm_kernel<<<gridBig, thr>>>(hn, dWih + (size_t)EE * G4H, nullptr, pre_d, G4H, HH, 1, 1);
    gemm_kernel<<<gridSml, thr>>>(hn, W1, nullptr, q, WT, HH, 0, 1);
    gemm_kernel<<<gridSml, thr>>>(hb, W1 + (size_t)HH * WT, nullptr, q, WT, HH, 0, 1);

    // 11-12: decoder recurrence + final projection
    lstm_kernel<<<128, 512>>>(pre_d, dWhh, dh, hn, 0);
    gemm_kernel<<<gridSml, thr>>>(dh, W4, nullptr, p, WT, HH, 0, 1);

    // 13: decisions
    decide_kernel<<<BB, 256>>>(q, p, vt1, out);
}